// round 3
// baseline (speedup 1.0000x reference)
#include <cuda_runtime.h>
#include <cstdint>

// ---------------------------------------------------------------------------
// MultiHeadAttention forward.
//   B=4, S=2048, D=1024, H=16, depth=64
// Projections + output GEMM: tf32 mma.sync (m16n8k8), fp32 accumulate.
// Attention: fp32 flash attention (online softmax), unchanged baseline.
// ---------------------------------------------------------------------------

#define BATCH   4
#define SLEN    2048
#define DMODEL  1024
#define NHEADS  16
#define DEPTH   64
#define ELEMS   (BATCH * SLEN * DMODEL)   // 8,388,608

// Scratch (device globals; no allocation allowed in kernel_launch).
__device__ float g_qh[ELEMS];   // [B, H, S, depth]
__device__ float g_kh[ELEMS];   // [B, H, S, depth]
__device__ float g_vh[ELEMS];   // [B, H, S, depth]
__device__ float g_ctx[ELEMS];  // [B, S, D]

__device__ __forceinline__ float to_tf32(float x) {
    float y;
    asm("cvt.rna.tf32.f32 %0, %1;" : "=f"(y) : "f"(x));
    return y;
}

// ---------------------------------------------------------------------------
// tf32 GEMM: C = A[M=8192, K=1024] @ W[K=1024, N=1024] + bias
// Block tile 128x128, K-tile 32, 256 threads = 8 warps (4m x 2n),
// warp tile 32x64, mma.m16n8k8 tf32 (2 m-tiles x 8 n-tiles per warp).
// A-frags via ldmatrix.x4 (b16 view); B-frags via scalar LDS (conflict-free).
// ---------------------------------------------------------------------------
#define BK 32
#define LDA 36    // As row stride (floats): 4-bank shift/row -> LDSM conflict-free
#define LDB 136   // Bs row stride (floats): b-frag groups land on banks 8*tig

__global__ __launch_bounds__(256, 2)
void gemm_tf32_kernel(const float* __restrict__ A,
                      const float* __restrict__ W,
                      const float* __restrict__ bias,
                      float* __restrict__ C,
                      int split_heads)
{
    const int K = DMODEL, N = DMODEL;
    __shared__ float As[128][LDA];   // [m][k], tf32-rounded values
    __shared__ float Bs[BK][LDB];    // [k][n], tf32-rounded values

    const int tid    = threadIdx.x;
    const int lane   = tid & 31;
    const int wid    = tid >> 5;
    const int warp_m = wid >> 1;        // 0..3
    const int warp_n = wid & 1;         // 0..1
    const int gid    = lane >> 2;       // 0..7
    const int tig    = lane & 3;        // 0..3

    const int bm = blockIdx.y * 128;
    const int bn = blockIdx.x * 128;

    // global load mappings
    const int arow = tid >> 3;          // 0..31 (+32 per iter)
    const int akf4 = (tid & 7) * 4;     // k offset
    const int bkrow = tid >> 5;         // 0..7 (+8 per iter)
    const int bnf4  = (tid & 31) * 4;   // n offset

    // ldmatrix source row/col within warp's A slab
    const int lrow  = warp_m * 32 + (lane & 15);
    const int lhalf = (lane >> 4) * 4;  // 0 or 4 (fp32 cols)

    float acc[2][8][4];
#pragma unroll
    for (int i = 0; i < 2; i++)
#pragma unroll
        for (int j = 0; j < 8; j++)
#pragma unroll
            for (int v = 0; v < 4; v++) acc[i][j][v] = 0.f;

    for (int k0 = 0; k0 < K; k0 += BK) {
        // global prefetch into registers
        float4 pa[4], pb[4];
#pragma unroll
        for (int it = 0; it < 4; it++) {
            pa[it] = *(const float4*)(A + (bm + arow + it * 32) * K + k0 + akf4);
            pb[it] = *(const float4*)(W + (k0 + bkrow + it * 8) * N + bn + bnf4);
        }
        __syncthreads();   // previous tile's compute done
#pragma unroll
        for (int it = 0; it < 4; it++) {
            float4 a = pa[it];
            a.x = to_tf32(a.x); a.y = to_tf32(a.y);
            a.z = to_tf32(a.z); a.w = to_tf32(a.w);
            *(float4*)&As[arow + it * 32][akf4] = a;
            float4 b = pb[it];
            b.x = to_tf32(b.x); b.y = to_tf32(b.y);
            b.z = to_tf32(b.z); b.w = to_tf32(b.w);
            *(float4*)&Bs[bkrow + it * 8][bnf4] = b;
        }
        __syncthreads();

#pragma unroll
        for (int ks = 0; ks < 4; ks++) {
            const int k8 = ks * 8;
            // A fragments: one ldmatrix.x4 per m-tile
            uint32_t af[2][4];
#pragma unroll
            for (int mt = 0; mt < 2; mt++) {
                uint32_t saddr = (uint32_t)__cvta_generic_to_shared(
                    &As[lrow + mt * 16][k8 + lhalf]);
                asm volatile(
                    "ldmatrix.sync.aligned.m8n8.x4.shared.b16 {%0,%1,%2,%3}, [%4];"
                    : "=r"(af[mt][0]), "=r"(af[mt][1]),
                      "=r"(af[mt][2]), "=r"(af[mt][3])
                    : "r"(saddr));
            }
#pragma unroll
            for (int j = 0; j < 8; j++) {
                const int ncol = warp_n * 64 + j * 8 + gid;
                uint32_t b0 = __float_as_uint(Bs[k8 + tig][ncol]);
                uint32_t b1 = __float_as_uint(Bs[k8 + tig + 4][ncol]);
#pragma unroll
                for (int mt = 0; mt < 2; mt++) {
                    asm volatile(
                        "mma.sync.aligned.m16n8k8.row.col.f32.tf32.tf32.f32 "
                        "{%0,%1,%2,%3}, {%4,%5,%6,%7}, {%8,%9}, {%0,%1,%2,%3};"
                        : "+f"(acc[mt][j][0]), "+f"(acc[mt][j][1]),
                          "+f"(acc[mt][j][2]), "+f"(acc[mt][j][3])
                        : "r"(af[mt][0]), "r"(af[mt][1]),
                          "r"(af[mt][2]), "r"(af[mt][3]),
                          "r"(b0), "r"(b1));
                }
            }
        }
    }

    // epilogue: c0,c1 -> (row+gid, col..col+1); c2,c3 -> (row+gid+8, ...)
#pragma unroll
    for (int mt = 0; mt < 2; mt++) {
        const int row0 = bm + warp_m * 32 + mt * 16 + gid;
#pragma unroll
        for (int j = 0; j < 8; j++) {
            const int gcol = bn + warp_n * 64 + j * 8 + tig * 2;
            const float bz0 = bias[gcol], bz1 = bias[gcol + 1];
#pragma unroll
            for (int half = 0; half < 2; half++) {
                const int grow = row0 + half * 8;
                float2 rv;
                rv.x = acc[mt][j][half * 2 + 0] + bz0;
                rv.y = acc[mt][j][half * 2 + 1] + bz1;
                if (split_heads) {
                    const int bb = grow >> 11;
                    const int ss = grow & (SLEN - 1);
                    const int hh = gcol >> 6;
                    const int dd = gcol & (DEPTH - 1);
                    *(float2*)&C[(((bb * NHEADS + hh) * SLEN) + ss) * DEPTH + dd] = rv;
                } else {
                    *(float2*)&C[grow * DMODEL + gcol] = rv;
                }
            }
        }
    }
}

// ---------------------------------------------------------------------------
// Flash attention (fp32, online softmax). Unchanged from baseline.
// Grid: (S/64, H, B). Block: 256 threads.
// ---------------------------------------------------------------------------
__global__ __launch_bounds__(256, 2)
void attn_kernel(const float* __restrict__ qh,
                 const float* __restrict__ kh,
                 const float* __restrict__ vh,
                 const int*   __restrict__ mask,
                 float* __restrict__ ctx)
{
    __shared__ float Kt[64 * 64];  // Kt[k*64 + j]
    __shared__ float Vs[64 * 64];  // Vs[j*64 + d]
    __shared__ float Ps[64 * 64];  // Ps[j*64 + r]

    const int tid = threadIdx.x;
    const int r   = tid >> 2;   // 0..63
    const int c   = tid & 3;    // 0..3
    const int qt  = blockIdx.x;
    const int h   = blockIdx.y;
    const int b   = blockIdx.z;

    const int bh_base = (b * NHEADS + h) * SLEN;
    const int qrow    = qt * 64 + r;

    float Qreg[64];
    {
        const float* qptr = qh + (bh_base + qrow) * DEPTH;
#pragma unroll
        for (int k4 = 0; k4 < 16; k4++) {
            float4 v = *(const float4*)(qptr + k4 * 4);
            Qreg[k4 * 4 + 0] = v.x;
            Qreg[k4 * 4 + 1] = v.y;
            Qreg[k4 * 4 + 2] = v.z;
            Qreg[k4 * 4 + 3] = v.w;
        }
    }

    float acc[16];
#pragma unroll
    for (int i = 0; i < 16; i++) acc[i] = 0.f;
    float mrun = -1e30f;
    float lrun = 0.f;

    const int* mrow = mask + b * SLEN;

    for (int kt = 0; kt < SLEN / 64; kt++) {
        const int kbase = (bh_base + kt * 64) * DEPTH;

        __syncthreads();
#pragma unroll
        for (int i = 0; i < 4; i++) {
            const int l  = tid + i * 256;
            const int j  = l >> 4;
            const int k4 = (l & 15) * 4;
            float4 kv = *(const float4*)(kh + kbase + j * DEPTH + k4);
            Kt[(k4 + 0) * 64 + j] = kv.x;
            Kt[(k4 + 1) * 64 + j] = kv.y;
            Kt[(k4 + 2) * 64 + j] = kv.z;
            Kt[(k4 + 3) * 64 + j] = kv.w;
            float4 vv = *(const float4*)(vh + kbase + j * DEPTH + k4);
            *(float4*)&Vs[j * 64 + k4] = vv;
        }
        __syncthreads();

        float s[16];
#pragma unroll
        for (int jj = 0; jj < 16; jj++) s[jj] = 0.f;
#pragma unroll
        for (int k = 0; k < 64; k++) {
            const float qv = Qreg[k];
            const float4* krow = (const float4*)&Kt[k * 64 + c * 16];
#pragma unroll
            for (int g = 0; g < 4; g++) {
                float4 kv = krow[g];
                s[g * 4 + 0] = fmaf(qv, kv.x, s[g * 4 + 0]);
                s[g * 4 + 1] = fmaf(qv, kv.y, s[g * 4 + 1]);
                s[g * 4 + 2] = fmaf(qv, kv.z, s[g * 4 + 2]);
                s[g * 4 + 3] = fmaf(qv, kv.w, s[g * 4 + 3]);
            }
        }

        const int* mptr = mrow + kt * 64 + c * 16;
        float tmax = -1e30f;
#pragma unroll
        for (int jj = 0; jj < 16; jj++) {
            float sv = s[jj] * 0.125f + (float)mptr[jj] * (-1000000000.0f);
            s[jj] = sv;
            tmax = fmaxf(tmax, sv);
        }
        tmax = fmaxf(tmax, __shfl_xor_sync(0xffffffffu, tmax, 1));
        tmax = fmaxf(tmax, __shfl_xor_sync(0xffffffffu, tmax, 2));
        const float mnew = fmaxf(mrun, tmax);
        const float corr = __expf(mrun - mnew);
        float rsum = 0.f;
#pragma unroll
        for (int jj = 0; jj < 16; jj++) {
            float p = __expf(s[jj] - mnew);
            rsum += p;
            Ps[(c * 16 + jj) * 64 + r] = p;
        }
        rsum += __shfl_xor_sync(0xffffffffu, rsum, 1);
        rsum += __shfl_xor_sync(0xffffffffu, rsum, 2);
        lrun = lrun * corr + rsum;
        mrun = mnew;
#pragma unroll
        for (int i = 0; i < 16; i++) acc[i] *= corr;

        __syncwarp();

        for (int j = 0; j < 64; j++) {
            const float p = Ps[j * 64 + r];
            const float4* vrow = (const float4*)&Vs[j * 64 + c * 16];
#pragma unroll
            for (int g = 0; g < 4; g++) {
                float4 vv = vrow[g];
                acc[g * 4 + 0] = fmaf(p, vv.x, acc[g * 4 + 0]);
                acc[g * 4 + 1] = fmaf(p, vv.y, acc[g * 4 + 1]);
                acc[g * 4 + 2] = fmaf(p, vv.z, acc[g * 4 + 2]);
                acc[g * 4 + 3] = fmaf(p, vv.w, acc[g * 4 + 3]);
            }
        }
    }

    const float inv = 1.f / lrun;
    const int obase = (b * SLEN + qrow) * DMODEL + h * DEPTH + c * 16;
#pragma unroll
    for (int g = 0; g < 4; g++) {
        float4 o;
        o.x = acc[g * 4 + 0] * inv;
        o.y = acc[g * 4 + 1] * inv;
        o.z = acc[g * 4 + 2] * inv;
        o.w = acc[g * 4 + 3] * inv;
        *(float4*)&ctx[obase + g * 4] = o;
    }
}

// ---------------------------------------------------------------------------
extern "C" void kernel_launch(void* const* d_in, const int* in_sizes, int n_in,
                              void* d_out, int out_size)
{
    const float* v    = (const float*)d_in[0];
    const float* k    = (const float*)d_in[1];
    const float* q    = (const float*)d_in[2];
    const int*   mask = (const int*)  d_in[3];
    const float* Wq   = (const float*)d_in[4];
    const float* bq   = (const float*)d_in[5];
    const float* Wk   = (const float*)d_in[6];
    const float* bk   = (const float*)d_in[7];
    const float* Wv   = (const float*)d_in[8];
    const float* bv   = (const float*)d_in[9];
    const float* Wo   = (const float*)d_in[10];
    const float* bo   = (const float*)d_in[11];
    float* out = (float*)d_out;

    float *qh, *kh, *vh, *ctx;
    cudaGetSymbolAddress((void**)&qh,  g_qh);
    cudaGetSymbolAddress((void**)&kh,  g_kh);
    cudaGetSymbolAddress((void**)&vh,  g_vh);
    cudaGetSymbolAddress((void**)&ctx, g_ctx);

    dim3 ggrid(DMODEL / 128, (BATCH * SLEN) / 128);   // (8, 64)

    gemm_tf32_kernel<<<ggrid, 256>>>(q, Wq, bq, qh, 1);
    gemm_tf32_kernel<<<ggrid, 256>>>(k, Wk, bk, kh, 1);
    gemm_tf32_kernel<<<ggrid, 256>>>(v, Wv, bv, vh, 1);

    attn_kernel<<<dim3(SLEN / 64, NHEADS, BATCH), 256>>>(qh, kh, vh, mask, ctx);

    gemm_tf32_kernel<<<ggrid, 256>>>(ctx, Wo, bo, out, 0);
}

// round 4
// speedup vs baseline: 7.2162x; 7.2162x over previous
#include <cuda_runtime.h>
#include <cstdint>

// ---------------------------------------------------------------------------
// MultiHeadAttention forward.
//   B=4, S=2048, D=1024, H=16, depth=64
// Projections + output GEMM: tf32 mma.sync (m16n8k8), fp32 accumulate.
// Attention: tf32 mma.sync flash attention, log2-domain online softmax with
// polynomial exp2 (MUFU-free).
// ---------------------------------------------------------------------------

#define BATCH   4
#define SLEN    2048
#define DMODEL  1024
#define NHEADS  16
#define DEPTH   64
#define ELEMS   (BATCH * SLEN * DMODEL)   // 8,388,608

__device__ float g_qh[ELEMS];   // [B, H, S, depth]
__device__ float g_kh[ELEMS];   // [B, H, S, depth]
__device__ float g_vh[ELEMS];   // [B, H, S, depth]
__device__ float g_ctx[ELEMS];  // [B, S, D]

__device__ __forceinline__ float to_tf32(float x) {
    float y;
    asm("cvt.rna.tf32.f32 %0, %1;" : "=f"(y) : "f"(x));
    return y;
}

// exp2 without MUFU: round-to-int via magic constant, deg-5 Taylor on
// f in [-0.5, 0.5], exponent patch via integer add. Valid for t in [-100, 0].
__device__ __forceinline__ float exp2p(float t) {
    t = fmaxf(t, -100.0f);
    const float MAGIC = 12582912.0f;            // 2^23 + 2^22
    float r = t + MAGIC;
    int   ib = __float_as_int(r) << 23;         // round(t) << 23
    float f = t - (r - MAGIC);                  // f in [-0.5, 0.5]
    float p = 0.00133335581f;
    p = fmaf(p, f, 0.00961812911f);
    p = fmaf(p, f, 0.05550410866f);
    p = fmaf(p, f, 0.24022650700f);
    p = fmaf(p, f, 0.69314718056f);
    p = fmaf(p, f, 1.0f);
    return __int_as_float(__float_as_int(p) + ib);
}

// ---------------------------------------------------------------------------
// tf32 GEMM: C = A[M=8192, K=1024] @ W[K=1024, N=1024] + bias  (unchanged,
// validated at 143 TF/s, rel_err model confirmed).
// ---------------------------------------------------------------------------
#define BK 32
#define LDA 36
#define LDB 136

__global__ __launch_bounds__(256, 2)
void gemm_tf32_kernel(const float* __restrict__ A,
                      const float* __restrict__ W,
                      const float* __restrict__ bias,
                      float* __restrict__ C,
                      int split_heads)
{
    const int K = DMODEL, N = DMODEL;
    __shared__ float As[128][LDA];
    __shared__ float Bs[BK][LDB];

    const int tid    = threadIdx.x;
    const int lane   = tid & 31;
    const int wid    = tid >> 5;
    const int warp_m = wid >> 1;
    const int warp_n = wid & 1;
    const int gid    = lane >> 2;
    const int tig    = lane & 3;

    const int bm = blockIdx.y * 128;
    const int bn = blockIdx.x * 128;

    const int arow  = tid >> 3;
    const int akf4  = (tid & 7) * 4;
    const int bkrow = tid >> 5;
    const int bnf4  = (tid & 31) * 4;

    const int lrow  = warp_m * 32 + (lane & 15);
    const int lhalf = (lane >> 4) * 4;

    float acc[2][8][4];
#pragma unroll
    for (int i = 0; i < 2; i++)
#pragma unroll
        for (int j = 0; j < 8; j++)
#pragma unroll
            for (int v = 0; v < 4; v++) acc[i][j][v] = 0.f;

    for (int k0 = 0; k0 < K; k0 += BK) {
        float4 pa[4], pb[4];
#pragma unroll
        for (int it = 0; it < 4; it++) {
            pa[it] = *(const float4*)(A + (bm + arow + it * 32) * K + k0 + akf4);
            pb[it] = *(const float4*)(W + (k0 + bkrow + it * 8) * N + bn + bnf4);
        }
        __syncthreads();
#pragma unroll
        for (int it = 0; it < 4; it++) {
            float4 a = pa[it];
            a.x = to_tf32(a.x); a.y = to_tf32(a.y);
            a.z = to_tf32(a.z); a.w = to_tf32(a.w);
            *(float4*)&As[arow + it * 32][akf4] = a;
            float4 b = pb[it];
            b.x = to_tf32(b.x); b.y = to_tf32(b.y);
            b.z = to_tf32(b.z); b.w = to_tf32(b.w);
            *(float4*)&Bs[bkrow + it * 8][bnf4] = b;
        }
        __syncthreads();

#pragma unroll
        for (int ks = 0; ks < 4; ks++) {
            const int k8 = ks * 8;
            uint32_t af[2][4];
#pragma unroll
            for (int mt = 0; mt < 2; mt++) {
                uint32_t saddr = (uint32_t)__cvta_generic_to_shared(
                    &As[lrow + mt * 16][k8 + lhalf]);
                asm volatile(
                    "ldmatrix.sync.aligned.m8n8.x4.shared.b16 {%0,%1,%2,%3}, [%4];"
                    : "=r"(af[mt][0]), "=r"(af[mt][1]),
                      "=r"(af[mt][2]), "=r"(af[mt][3])
                    : "r"(saddr));
            }
#pragma unroll
            for (int j = 0; j < 8; j++) {
                const int ncol = warp_n * 64 + j * 8 + gid;
                uint32_t b0 = __float_as_uint(Bs[k8 + tig][ncol]);
                uint32_t b1 = __float_as_uint(Bs[k8 + tig + 4][ncol]);
#pragma unroll
                for (int mt = 0; mt < 2; mt++) {
                    asm volatile(
                        "mma.sync.aligned.m16n8k8.row.col.f32.tf32.tf32.f32 "
                        "{%0,%1,%2,%3}, {%4,%5,%6,%7}, {%8,%9}, {%0,%1,%2,%3};"
                        : "+f"(acc[mt][j][0]), "+f"(acc[mt][j][1]),
                          "+f"(acc[mt][j][2]), "+f"(acc[mt][j][3])
                        : "r"(af[mt][0]), "r"(af[mt][1]),
                          "r"(af[mt][2]), "r"(af[mt][3]),
                          "r"(b0), "r"(b1));
                }
            }
        }
    }

#pragma unroll
    for (int mt = 0; mt < 2; mt++) {
        const int row0 = bm + warp_m * 32 + mt * 16 + gid;
#pragma unroll
        for (int j = 0; j < 8; j++) {
            const int gcol = bn + warp_n * 64 + j * 8 + tig * 2;
            const float bz0 = bias[gcol], bz1 = bias[gcol + 1];
#pragma unroll
            for (int half = 0; half < 2; half++) {
                const int grow = row0 + half * 8;
                float2 rv;
                rv.x = acc[mt][j][half * 2 + 0] + bz0;
                rv.y = acc[mt][j][half * 2 + 1] + bz1;
                if (split_heads) {
                    const int bb = grow >> 11;
                    const int ss = grow & (SLEN - 1);
                    const int hh = gcol >> 6;
                    const int dd = gcol & (DEPTH - 1);
                    *(float2*)&C[(((bb * NHEADS + hh) * SLEN) + ss) * DEPTH + dd] = rv;
                } else {
                    *(float2*)&C[grow * DMODEL + gcol] = rv;
                }
            }
        }
    }
}

// ---------------------------------------------------------------------------
// Tensor-core flash attention (tf32 mma, fp32 accumulate).
// Grid (S/128, H, B), 256 threads = 8 warps; warp owns 16 query rows.
// K-tile = 64 keys. Q a-frags preloaded to registers (Q smem is a union with
// the K/V tile buffers). Softmax in log2 domain, polynomial exp2.
// P (S-frag layout) -> a-frag layout via register shuffles, no smem staging.
// ---------------------------------------------------------------------------
#define SCL 0.18033688f          // 0.125 * log2(e)
#define MASKC (-1.44269504e9f)   // -1e9 * log2(e)

__global__ __launch_bounds__(256, 2)
void attn_mma_kernel(const float* __restrict__ qh,
                     const float* __restrict__ kh,
                     const float* __restrict__ vh,
                     const int*   __restrict__ mask,
                     float* __restrict__ ctx)
{
    __shared__ union {
        float q[128][68];                       // Q staging (pre-loop only)
        struct { float k[64][72]; float v[64][72]; } kv;
    } sm;
    __shared__ float msk[64];

    const int tid  = threadIdx.x;
    const int lane = tid & 31;
    const int wid  = tid >> 5;
    const int gid  = lane >> 2;
    const int tig  = lane & 3;

    const int qt0 = blockIdx.x * 128;
    const int h   = blockIdx.y;
    const int b   = blockIdx.z;
    const int bh  = (b * NHEADS + h) * SLEN;

    // ---- stage Q tile (tf32-rounded), ldmatrix a-frags to registers ----
#pragma unroll
    for (int i = 0; i < 8; i++) {
        const int idx = tid + i * 256;          // 2048 float4 slots
        const int row = idx >> 4;
        const int c4  = (idx & 15) * 4;
        float4 qv = *(const float4*)(qh + (bh + qt0 + row) * DEPTH + c4);
        qv.x = to_tf32(qv.x); qv.y = to_tf32(qv.y);
        qv.z = to_tf32(qv.z); qv.w = to_tf32(qv.w);
        *(float4*)&sm.q[row][c4] = qv;
    }
    __syncthreads();

    uint32_t qf[8][4];
    {
        const int lrow = wid * 16 + (lane & 15);
        const int lco  = (lane >> 4) * 4;
#pragma unroll
        for (int ks = 0; ks < 8; ks++) {
            uint32_t saddr = (uint32_t)__cvta_generic_to_shared(
                &sm.q[lrow][ks * 8 + lco]);
            asm volatile(
                "ldmatrix.sync.aligned.m8n8.x4.shared.b16 {%0,%1,%2,%3}, [%4];"
                : "=r"(qf[ks][0]), "=r"(qf[ks][1]),
                  "=r"(qf[ks][2]), "=r"(qf[ks][3])
                : "r"(saddr));
        }
    }

    float acc[8][4];
#pragma unroll
    for (int nt = 0; nt < 8; nt++)
#pragma unroll
        for (int e = 0; e < 4; e++) acc[nt][e] = 0.f;
    float mr0 = -1e30f, mr1 = -1e30f;
    float lr0 = 0.f,    lr1 = 0.f;

    for (int kt = 0; kt < SLEN / 64; kt++) {
        __syncthreads();   // prior compute done (also guards Q-staging union)
        const int kvbase = (bh + kt * 64) * DEPTH;
#pragma unroll
        for (int i = 0; i < 4; i++) {
            const int idx = tid + i * 256;      // 1024 float4 slots per tensor
            const int row = idx >> 4;
            const int c4  = (idx & 15) * 4;
            float4 kv = *(const float4*)(kh + kvbase + row * DEPTH + c4);
            kv.x = to_tf32(kv.x); kv.y = to_tf32(kv.y);
            kv.z = to_tf32(kv.z); kv.w = to_tf32(kv.w);
            *(float4*)&sm.kv.k[row][c4] = kv;
            float4 vv = *(const float4*)(vh + kvbase + row * DEPTH + c4);
            vv.x = to_tf32(vv.x); vv.y = to_tf32(vv.y);
            vv.z = to_tf32(vv.z); vv.w = to_tf32(vv.w);
            *(float4*)&sm.kv.v[row][c4] = vv;
        }
        if (tid < 64)
            msk[tid] = MASKC * (float)mask[b * SLEN + kt * 64 + tid];
        __syncthreads();

        // ---- S = Q @ K^T (raw dots; scale folded later) ----
        float s[8][4];
#pragma unroll
        for (int nt = 0; nt < 8; nt++)
#pragma unroll
            for (int e = 0; e < 4; e++) s[nt][e] = 0.f;
#pragma unroll
        for (int k8 = 0; k8 < 8; k8++) {
#pragma unroll
            for (int nt = 0; nt < 8; nt++) {
                uint32_t b0 = __float_as_uint(sm.kv.k[nt * 8 + gid][k8 * 8 + tig]);
                uint32_t b1 = __float_as_uint(sm.kv.k[nt * 8 + gid][k8 * 8 + tig + 4]);
                asm volatile(
                    "mma.sync.aligned.m16n8k8.row.col.f32.tf32.tf32.f32 "
                    "{%0,%1,%2,%3}, {%4,%5,%6,%7}, {%8,%9}, {%0,%1,%2,%3};"
                    : "+f"(s[nt][0]), "+f"(s[nt][1]),
                      "+f"(s[nt][2]), "+f"(s[nt][3])
                    : "r"(qf[k8][0]), "r"(qf[k8][1]),
                      "r"(qf[k8][2]), "r"(qf[k8][3]),
                      "r"(b0), "r"(b1));
            }
        }

        // ---- scale to log2 domain + mask, row max ----
        float tm0 = -1e30f, tm1 = -1e30f;
#pragma unroll
        for (int nt = 0; nt < 8; nt++) {
            const float mk0 = msk[nt * 8 + tig * 2];
            const float mk1 = msk[nt * 8 + tig * 2 + 1];
            s[nt][0] = fmaf(s[nt][0], SCL, mk0);
            s[nt][1] = fmaf(s[nt][1], SCL, mk1);
            s[nt][2] = fmaf(s[nt][2], SCL, mk0);
            s[nt][3] = fmaf(s[nt][3], SCL, mk1);
            tm0 = fmaxf(tm0, fmaxf(s[nt][0], s[nt][1]));
            tm1 = fmaxf(tm1, fmaxf(s[nt][2], s[nt][3]));
        }
        tm0 = fmaxf(tm0, __shfl_xor_sync(0xffffffffu, tm0, 1));
        tm0 = fmaxf(tm0, __shfl_xor_sync(0xffffffffu, tm0, 2));
        tm1 = fmaxf(tm1, __shfl_xor_sync(0xffffffffu, tm1, 1));
        tm1 = fmaxf(tm1, __shfl_xor_sync(0xffffffffu, tm1, 2));

        const float mn0 = fmaxf(mr0, tm0);
        const float mn1 = fmaxf(mr1, tm1);
        const float c0  = exp2p(mr0 - mn0);
        const float c1  = exp2p(mr1 - mn1);

        float rs0 = 0.f, rs1 = 0.f;
#pragma unroll
        for (int nt = 0; nt < 8; nt++) {
            float p0 = exp2p(s[nt][0] - mn0);
            float p1 = exp2p(s[nt][1] - mn0);
            float p2 = exp2p(s[nt][2] - mn1);
            float p3 = exp2p(s[nt][3] - mn1);
            rs0 += p0 + p1;
            rs1 += p2 + p3;
            s[nt][0] = to_tf32(p0);
            s[nt][1] = to_tf32(p1);
            s[nt][2] = to_tf32(p2);
            s[nt][3] = to_tf32(p3);
        }
        rs0 += __shfl_xor_sync(0xffffffffu, rs0, 1);
        rs0 += __shfl_xor_sync(0xffffffffu, rs0, 2);
        rs1 += __shfl_xor_sync(0xffffffffu, rs1, 1);
        rs1 += __shfl_xor_sync(0xffffffffu, rs1, 2);
        lr0 = lr0 * c0 + rs0;
        lr1 = lr1 * c1 + rs1;
        mr0 = mn0;
        mr1 = mn1;
#pragma unroll
        for (int nt = 0; nt < 8; nt++) {
            acc[nt][0] *= c0; acc[nt][1] *= c0;
            acc[nt][2] *= c1; acc[nt][3] *= c1;
        }

        // ---- acc += P @ V : S-frag -> a-frag via shuffles ----
        const int src0 = gid * 4 + (tig >> 1);
        const int src1 = src0 + 2;
        const bool odd = (tig & 1);
#pragma unroll
        for (int kc = 0; kc < 8; kc++) {
            float x0 = __shfl_sync(0xffffffffu, s[kc][0], src0);
            float x1 = __shfl_sync(0xffffffffu, s[kc][1], src0);
            float x2 = __shfl_sync(0xffffffffu, s[kc][2], src0);
            float x3 = __shfl_sync(0xffffffffu, s[kc][3], src0);
            float y0 = __shfl_sync(0xffffffffu, s[kc][0], src1);
            float y1 = __shfl_sync(0xffffffffu, s[kc][1], src1);
            float y2 = __shfl_sync(0xffffffffu, s[kc][2], src1);
            float y3 = __shfl_sync(0xffffffffu, s[kc][3], src1);
            uint32_t a0 = __float_as_uint(odd ? x1 : x0);
            uint32_t a1 = __float_as_uint(odd ? x3 : x2);
            uint32_t a2 = __float_as_uint(odd ? y1 : y0);
            uint32_t a3 = __float_as_uint(odd ? y3 : y2);
#pragma unroll
            for (int nt = 0; nt < 8; nt++) {
                uint32_t b0 = __float_as_uint(sm.kv.v[kc * 8 + tig][nt * 8 + gid]);
                uint32_t b1 = __float_as_uint(sm.kv.v[kc * 8 + tig + 4][nt * 8 + gid]);
                asm volatile(
                    "mma.sync.aligned.m16n8k8.row.col.f32.tf32.tf32.f32 "
                    "{%0,%1,%2,%3}, {%4,%5,%6,%7}, {%8,%9}, {%0,%1,%2,%3};"
                    : "+f"(acc[nt][0]), "+f"(acc[nt][1]),
                      "+f"(acc[nt][2]), "+f"(acc[nt][3])
                    : "r"(a0), "r"(a1), "r"(a2), "r"(a3),
                      "r"(b0), "r"(b1));
            }
        }
    }

    // ---- epilogue: ctx[b, q, h*64 + d] = acc / l ----
    const float inv0 = 1.f / lr0;
    const float inv1 = 1.f / lr1;
    const int r0 = qt0 + wid * 16 + gid;
    const int r1 = r0 + 8;
#pragma unroll
    for (int nt = 0; nt < 8; nt++) {
        const int col = h * DEPTH + nt * 8 + tig * 2;
        float2 o0, o1;
        o0.x = acc[nt][0] * inv0; o0.y = acc[nt][1] * inv0;
        o1.x = acc[nt][2] * inv1; o1.y = acc[nt][3] * inv1;
        *(float2*)&ctx[(b * SLEN + r0) * DMODEL + col] = o0;
        *(float2*)&ctx[(b * SLEN + r1) * DMODEL + col] = o1;
    }
}

// ---------------------------------------------------------------------------
extern "C" void kernel_launch(void* const* d_in, const int* in_sizes, int n_in,
                              void* d_out, int out_size)
{
    const float* v    = (const float*)d_in[0];
    const float* k    = (const float*)d_in[1];
    const float* q    = (const float*)d_in[2];
    const int*   mask = (const int*)  d_in[3];
    const float* Wq   = (const float*)d_in[4];
    const float* bq   = (const float*)d_in[5];
    const float* Wk   = (const float*)d_in[6];
    const float* bk   = (const float*)d_in[7];
    const float* Wv   = (const float*)d_in[8];
    const float* bv   = (const float*)d_in[9];
    const float* Wo   = (const float*)d_in[10];
    const float* bo   = (const float*)d_in[11];
    float* out = (float*)d_out;

    float *qh, *kh, *vh, *ctx;
    cudaGetSymbolAddress((void**)&qh,  g_qh);
    cudaGetSymbolAddress((void**)&kh,  g_kh);
    cudaGetSymbolAddress((void**)&vh,  g_vh);
    cudaGetSymbolAddress((void**)&ctx, g_ctx);

    dim3 ggrid(DMODEL / 128, (BATCH * SLEN) / 128);   // (8, 64)

    gemm_tf32_kernel<<<ggrid, 256>>>(q, Wq, bq, qh, 1);
    gemm_tf32_kernel<<<ggrid, 256>>>(k, Wk, bk, kh, 1);
    gemm_tf32_kernel<<<ggrid, 256>>>(v, Wv, bv, vh, 1);

    attn_mma_kernel<<<dim3(SLEN / 128, NHEADS, BATCH), 256>>>(qh, kh, vh, mask, ctx);

    gemm_tf32_kernel<<<ggrid, 256>>>(ctx, Wo, bo, out, 0);
}

// round 5
// speedup vs baseline: 7.9205x; 1.0976x over previous
#include <cuda_runtime.h>
#include <cstdint>

// ---------------------------------------------------------------------------
// MultiHeadAttention forward.
//   B=4, S=2048, D=1024, H=16, depth=64
// Projections + output GEMM: tf32 mma.sync (m16n8k8), fp32 accumulate.
// Attention: tf32 mma.sync flash attention; K/V operand fragments via
// conflict-free ldmatrix.x4; V pre-transposed by its projection GEMM.
// Softmax in log2 domain with polynomial exp2 (MUFU-free).
// ---------------------------------------------------------------------------

#define BATCH   4
#define SLEN    2048
#define DMODEL  1024
#define NHEADS  16
#define DEPTH   64
#define ELEMS   (BATCH * SLEN * DMODEL)   // 8,388,608

__device__ float g_qh[ELEMS];   // [B, H, S, depth]
__device__ float g_kh[ELEMS];   // [B, H, S, depth]
__device__ float g_vh[ELEMS];   // [B, H, depth, S]  (transposed!)
__device__ float g_ctx[ELEMS];  // [B, S, D]

__device__ __forceinline__ float to_tf32(float x) {
    float y;
    asm("cvt.rna.tf32.f32 %0, %1;" : "=f"(y) : "f"(x));
    return y;
}

// exp2 without MUFU: round via magic constant, deg-5 Taylor on [-0.5,0.5].
__device__ __forceinline__ float exp2p(float t) {
    t = fmaxf(t, -100.0f);
    const float MAGIC = 12582912.0f;            // 2^23 + 2^22
    float r = t + MAGIC;
    int   ib = __float_as_int(r) << 23;
    float f = t - (r - MAGIC);
    float p = 0.00133335581f;
    p = fmaf(p, f, 0.00961812911f);
    p = fmaf(p, f, 0.05550410866f);
    p = fmaf(p, f, 0.24022650700f);
    p = fmaf(p, f, 0.69314718056f);
    p = fmaf(p, f, 1.0f);
    return __int_as_float(__float_as_int(p) + ib);
}

// ---------------------------------------------------------------------------
// tf32 GEMM: C = A[8192,1024] @ W[1024,1024] + bias.
// mode: 0 = row-major C; 1 = split-heads [B,H,S,d]; 2 = split-heads
// transposed [B,H,d,S] (for V).
// ---------------------------------------------------------------------------
#define BK 32
#define LDA 36
#define LDB 136

__global__ __launch_bounds__(256, 2)
void gemm_tf32_kernel(const float* __restrict__ A,
                      const float* __restrict__ W,
                      const float* __restrict__ bias,
                      float* __restrict__ C,
                      int mode)
{
    const int K = DMODEL, N = DMODEL;
    __shared__ float As[128][LDA];
    __shared__ float Bs[BK][LDB];

    const int tid    = threadIdx.x;
    const int lane   = tid & 31;
    const int wid    = tid >> 5;
    const int warp_m = wid >> 1;
    const int warp_n = wid & 1;
    const int gid    = lane >> 2;
    const int tig    = lane & 3;

    const int bm = blockIdx.y * 128;
    const int bn = blockIdx.x * 128;

    const int arow  = tid >> 3;
    const int akf4  = (tid & 7) * 4;
    const int bkrow = tid >> 5;
    const int bnf4  = (tid & 31) * 4;

    const int lrow  = warp_m * 32 + (lane & 15);
    const int lhalf = (lane >> 4) * 4;

    float acc[2][8][4];
#pragma unroll
    for (int i = 0; i < 2; i++)
#pragma unroll
        for (int j = 0; j < 8; j++)
#pragma unroll
            for (int v = 0; v < 4; v++) acc[i][j][v] = 0.f;

    for (int k0 = 0; k0 < K; k0 += BK) {
        float4 pa[4], pb[4];
#pragma unroll
        for (int it = 0; it < 4; it++) {
            pa[it] = *(const float4*)(A + (bm + arow + it * 32) * K + k0 + akf4);
            pb[it] = *(const float4*)(W + (k0 + bkrow + it * 8) * N + bn + bnf4);
        }
        __syncthreads();
#pragma unroll
        for (int it = 0; it < 4; it++) {
            float4 a = pa[it];
            a.x = to_tf32(a.x); a.y = to_tf32(a.y);
            a.z = to_tf32(a.z); a.w = to_tf32(a.w);
            *(float4*)&As[arow + it * 32][akf4] = a;
            float4 b = pb[it];
            b.x = to_tf32(b.x); b.y = to_tf32(b.y);
            b.z = to_tf32(b.z); b.w = to_tf32(b.w);
            *(float4*)&Bs[bkrow + it * 8][bnf4] = b;
        }
        __syncthreads();

#pragma unroll
        for (int ks = 0; ks < 4; ks++) {
            const int k8 = ks * 8;
            uint32_t af[2][4];
#pragma unroll
            for (int mt = 0; mt < 2; mt++) {
                uint32_t saddr = (uint32_t)__cvta_generic_to_shared(
                    &As[lrow + mt * 16][k8 + lhalf]);
                asm volatile(
                    "ldmatrix.sync.aligned.m8n8.x4.shared.b16 {%0,%1,%2,%3}, [%4];"
                    : "=r"(af[mt][0]), "=r"(af[mt][1]),
                      "=r"(af[mt][2]), "=r"(af[mt][3])
                    : "r"(saddr));
            }
#pragma unroll
            for (int j = 0; j < 8; j++) {
                const int ncol = warp_n * 64 + j * 8 + gid;
                uint32_t b0 = __float_as_uint(Bs[k8 + tig][ncol]);
                uint32_t b1 = __float_as_uint(Bs[k8 + tig + 4][ncol]);
#pragma unroll
                for (int mt = 0; mt < 2; mt++) {
                    asm volatile(
                        "mma.sync.aligned.m16n8k8.row.col.f32.tf32.tf32.f32 "
                        "{%0,%1,%2,%3}, {%4,%5,%6,%7}, {%8,%9}, {%0,%1,%2,%3};"
                        : "+f"(acc[mt][j][0]), "+f"(acc[mt][j][1]),
                          "+f"(acc[mt][j][2]), "+f"(acc[mt][j][3])
                        : "r"(af[mt][0]), "r"(af[mt][1]),
                          "r"(af[mt][2]), "r"(af[mt][3]),
                          "r"(b0), "r"(b1));
                }
            }
        }
    }

#pragma unroll
    for (int mt = 0; mt < 2; mt++) {
        const int row0 = bm + warp_m * 32 + mt * 16 + gid;
#pragma unroll
        for (int j = 0; j < 8; j++) {
            const int gcol = bn + warp_n * 64 + j * 8 + tig * 2;
            const float bz0 = bias[gcol], bz1 = bias[gcol + 1];
#pragma unroll
            for (int half = 0; half < 2; half++) {
                const int grow = row0 + half * 8;
                float2 rv;
                rv.x = acc[mt][j][half * 2 + 0] + bz0;
                rv.y = acc[mt][j][half * 2 + 1] + bz1;
                if (mode == 1) {
                    const int bb = grow >> 11;
                    const int ss = grow & (SLEN - 1);
                    const int hh = gcol >> 6;
                    const int dd = gcol & (DEPTH - 1);
                    *(float2*)&C[(((bb * NHEADS + hh) * SLEN) + ss) * DEPTH + dd] = rv;
                } else if (mode == 2) {
                    const int bb = grow >> 11;
                    const int ss = grow & (SLEN - 1);
                    const int hh = gcol >> 6;
                    const int dd = gcol & (DEPTH - 1);
                    float* p = &C[(((bb * NHEADS + hh) * DEPTH) + dd) * SLEN + ss];
                    p[0]    = rv.x;
                    p[SLEN] = rv.y;
                } else {
                    *(float2*)&C[grow * DMODEL + gcol] = rv;
                }
            }
        }
    }
}

// ---------------------------------------------------------------------------
// Tensor-core flash attention (tf32 mma, fp32 accumulate).
// Grid (S/128, H, B), 256 threads = 8 warps; warp owns 16 query rows.
// K-tile = 64 keys. K row-major [key][d], V transposed [d][key] in smem,
// both stride 68 (== 4 mod 32 -> conflict-free 8x8 fp32 ldmatrix tiles).
// Operand b-frags via ldmatrix.x4. Softmax in log2 domain.
// ---------------------------------------------------------------------------
#define SCL 0.18033688f          // 0.125 * log2(e)
#define MASKC (-1.44269504e9f)   // -1e9 * log2(e)
#define LDS68 68

__global__ __launch_bounds__(256, 2)
void attn_mma_kernel(const float* __restrict__ qh,
                     const float* __restrict__ kh,
                     const float* __restrict__ vt,   // [B,H,depth,S]
                     const int*   __restrict__ mask,
                     float* __restrict__ ctx)
{
    __shared__ union {
        float q[128][LDS68];                    // Q staging (pre-loop only)
        struct { float k[64][LDS68]; float v[64][LDS68]; } kv;
    } sm;
    __shared__ float msk[64];

    const int tid  = threadIdx.x;
    const int lane = tid & 31;
    const int wid  = tid >> 5;
    const int gid  = lane >> 2;
    const int tig  = lane & 3;

    const int qt0 = blockIdx.x * 128;
    const int h   = blockIdx.y;
    const int b   = blockIdx.z;
    const int bh  = (b * NHEADS + h) * SLEN;
    const int vtb = (b * NHEADS + h) * DEPTH;   // row base in [B*H, d, S]

    // ---- stage Q tile (tf32-rounded), ldmatrix a-frags to registers ----
#pragma unroll
    for (int i = 0; i < 8; i++) {
        const int idx = tid + i * 256;          // 2048 float4 slots
        const int row = idx >> 4;
        const int c4  = (idx & 15) * 4;
        float4 qv = *(const float4*)(qh + (bh + qt0 + row) * DEPTH + c4);
        qv.x = to_tf32(qv.x); qv.y = to_tf32(qv.y);
        qv.z = to_tf32(qv.z); qv.w = to_tf32(qv.w);
        *(float4*)&sm.q[row][c4] = qv;
    }
    __syncthreads();

    uint32_t qf[8][4];
    {
        const int lrow = wid * 16 + (lane & 15);
        const int lco  = (lane >> 4) * 4;
#pragma unroll
        for (int ks = 0; ks < 8; ks++) {
            uint32_t saddr = (uint32_t)__cvta_generic_to_shared(
                &sm.q[lrow][ks * 8 + lco]);
            asm volatile(
                "ldmatrix.sync.aligned.m8n8.x4.shared.b16 {%0,%1,%2,%3}, [%4];"
                : "=r"(qf[ks][0]), "=r"(qf[ks][1]),
                  "=r"(qf[ks][2]), "=r"(qf[ks][3])
                : "r"(saddr));
        }
    }

    // per-lane base offsets for b-frag ldmatrix.x4:
    //   lanes 0-7: tile0 rows, col+0 | 8-15: tile1 rows, col+4
    //   lanes 16-23: tile2 (+8 rows), col+0 | 24-31: tile3 (+8 rows), col+4
    const int bf_row = (lane & 7) + ((lane >> 4) << 3);
    const int bf_c4  = ((lane >> 3) & 1) * 4;

    float acc[8][4];
#pragma unroll
    for (int nt = 0; nt < 8; nt++)
#pragma unroll
        for (int e = 0; e < 4; e++) acc[nt][e] = 0.f;
    float mr0 = -1e30f, mr1 = -1e30f;
    float lr0 = 0.f,    lr1 = 0.f;

    for (int kt = 0; kt < SLEN / 64; kt++) {
        __syncthreads();   // prior compute done (also guards Q-staging union)
        const int kbase = (bh + kt * 64) * DEPTH;
#pragma unroll
        for (int i = 0; i < 4; i++) {
            const int idx = tid + i * 256;      // 1024 float4 slots
            const int row = idx >> 4;           // key row for K / d row for Vt
            const int c4  = (idx & 15) * 4;
            float4 kv = *(const float4*)(kh + kbase + row * DEPTH + c4);
            kv.x = to_tf32(kv.x); kv.y = to_tf32(kv.y);
            kv.z = to_tf32(kv.z); kv.w = to_tf32(kv.w);
            *(float4*)&sm.kv.k[row][c4] = kv;
            float4 vv = *(const float4*)(vt + (vtb + row) * SLEN + kt * 64 + c4);
            vv.x = to_tf32(vv.x); vv.y = to_tf32(vv.y);
            vv.z = to_tf32(vv.z); vv.w = to_tf32(vv.w);
            *(float4*)&sm.kv.v[row][c4] = vv;
        }
        if (tid < 64)
            msk[tid] = MASKC * (float)mask[b * SLEN + kt * 64 + tid];
        __syncthreads();

        const uint32_t kbase_s = (uint32_t)__cvta_generic_to_shared(
            &sm.kv.k[bf_row][bf_c4]);
        const uint32_t vbase_s = (uint32_t)__cvta_generic_to_shared(
            &sm.kv.v[bf_row][bf_c4]);

        // ---- S = Q @ K^T ----
        float s[8][4];
#pragma unroll
        for (int nt = 0; nt < 8; nt++)
#pragma unroll
            for (int e = 0; e < 4; e++) s[nt][e] = 0.f;
#pragma unroll
        for (int k8 = 0; k8 < 8; k8++) {
#pragma unroll
            for (int ntp = 0; ntp < 4; ntp++) {
                uint32_t r0, r1, r2, r3;
                asm volatile(
                    "ldmatrix.sync.aligned.m8n8.x4.shared.b16 {%0,%1,%2,%3}, [%4];"
                    : "=r"(r0), "=r"(r1), "=r"(r2), "=r"(r3)
                    : "r"(kbase_s + ntp * (16 * LDS68 * 4) + k8 * 32));
                asm volatile(
                    "mma.sync.aligned.m16n8k8.row.col.f32.tf32.tf32.f32 "
                    "{%0,%1,%2,%3}, {%4,%5,%6,%7}, {%8,%9}, {%0,%1,%2,%3};"
                    : "+f"(s[2 * ntp][0]), "+f"(s[2 * ntp][1]),
                      "+f"(s[2 * ntp][2]), "+f"(s[2 * ntp][3])
                    : "r"(qf[k8][0]), "r"(qf[k8][1]),
                      "r"(qf[k8][2]), "r"(qf[k8][3]),
                      "r"(r0), "r"(r1));
                asm volatile(
                    "mma.sync.aligned.m16n8k8.row.col.f32.tf32.tf32.f32 "
                    "{%0,%1,%2,%3}, {%4,%5,%6,%7}, {%8,%9}, {%0,%1,%2,%3};"
                    : "+f"(s[2 * ntp + 1][0]), "+f"(s[2 * ntp + 1][1]),
                      "+f"(s[2 * ntp + 1][2]), "+f"(s[2 * ntp + 1][3])
                    : "r"(qf[k8][0]), "r"(qf[k8][1]),
                      "r"(qf[k8][2]), "r"(qf[k8][3]),
                      "r"(r2), "r"(r3));
            }
        }

        // ---- scale to log2 domain + mask, row max ----
        float tm0 = -1e30f, tm1 = -1e30f;
#pragma unroll
        for (int nt = 0; nt < 8; nt++) {
            const float mk0 = msk[nt * 8 + tig * 2];
            const float mk1 = msk[nt * 8 + tig * 2 + 1];
            s[nt][0] = fmaf(s[nt][0], SCL, mk0);
            s[nt][1] = fmaf(s[nt][1], SCL, mk1);
            s[nt][2] = fmaf(s[nt][2], SCL, mk0);
            s[nt][3] = fmaf(s[nt][3], SCL, mk1);
            tm0 = fmaxf(tm0, fmaxf(s[nt][0], s[nt][1]));
            tm1 = fmaxf(tm1, fmaxf(s[nt][2], s[nt][3]));
        }
        tm0 = fmaxf(tm0, __shfl_xor_sync(0xffffffffu, tm0, 1));
        tm0 = fmaxf(tm0, __shfl_xor_sync(0xffffffffu, tm0, 2));
        tm1 = fmaxf(tm1, __shfl_xor_sync(0xffffffffu, tm1, 1));
        tm1 = fmaxf(tm1, __shfl_xor_sync(0xffffffffu, tm1, 2));

        const float mn0 = fmaxf(mr0, tm0);
        const float mn1 = fmaxf(mr1, tm1);
        const float c0  = exp2p(mr0 - mn0);
        const float c1  = exp2p(mr1 - mn1);

        float rs0 = 0.f, rs1 = 0.f;
#pragma unroll
        for (int nt = 0; nt < 8; nt++) {
            float p0 = exp2p(s[nt][0] - mn0);
            float p1 = exp2p(s[nt][1] - mn0);
            float p2 = exp2p(s[nt][2] - mn1);
            float p3 = exp2p(s[nt][3] - mn1);
            rs0 += p0 + p1;
            rs1 += p2 + p3;
            s[nt][0] = to_tf32(p0);
            s[nt][1] = to_tf32(p1);
            s[nt][2] = to_tf32(p2);
            s[nt][3] = to_tf32(p3);
        }
        rs0 += __shfl_xor_sync(0xffffffffu, rs0, 1);
        rs0 += __shfl_xor_sync(0xffffffffu, rs0, 2);
        rs1 += __shfl_xor_sync(0xffffffffu, rs1, 1);
        rs1 += __shfl_xor_sync(0xffffffffu, rs1, 2);
        lr0 = lr0 * c0 + rs0;
        lr1 = lr1 * c1 + rs1;
        mr0 = mn0;
        mr1 = mn1;
#pragma unroll
        for (int nt = 0; nt < 8; nt++) {
            acc[nt][0] *= c0; acc[nt][1] *= c0;
            acc[nt][2] *= c1; acc[nt][3] *= c1;
        }

        // ---- acc += P @ V : S-frag -> a-frag via shuffles; V via ldmatrix ----
        const int src0 = gid * 4 + (tig >> 1);
        const int src1 = src0 + 2;
        const bool odd = (tig & 1);
#pragma unroll
        for (int kc = 0; kc < 8; kc++) {
            float x0 = __shfl_sync(0xffffffffu, s[kc][0], src0);
            float x1 = __shfl_sync(0xffffffffu, s[kc][1], src0);
            float x2 = __shfl_sync(0xffffffffu, s[kc][2], src0);
            float x3 = __shfl_sync(0xffffffffu, s[kc][3], src0);
            float y0 = __shfl_sync(0xffffffffu, s[kc][0], src1);
            float y1 = __shfl_sync(0xffffffffu, s[kc][1], src1);
            float y2 = __shfl_sync(0xffffffffu, s[kc][2], src1);
            float y3 = __shfl_sync(0xffffffffu, s[kc][3], src1);
            uint32_t a0 = __float_as_uint(odd ? x1 : x0);
            uint32_t a1 = __float_as_uint(odd ? x3 : x2);
            uint32_t a2 = __float_as_uint(odd ? y1 : y0);
            uint32_t a3 = __float_as_uint(odd ? y3 : y2);
#pragma unroll
            for (int ntp = 0; ntp < 4; ntp++) {
                uint32_t r0, r1, r2, r3;
                asm volatile(
                    "ldmatrix.sync.aligned.m8n8.x4.shared.b16 {%0,%1,%2,%3}, [%4];"
                    : "=r"(r0), "=r"(r1), "=r"(r2), "=r"(r3)
                    : "r"(vbase_s + ntp * (16 * LDS68 * 4) + kc * 32));
                asm volatile(
                    "mma.sync.aligned.m16n8k8.row.col.f32.tf32.tf32.f32 "
                    "{%0,%1,%2,%3}, {%4,%5,%6,%7}, {%8,%9}, {%0,%1,%2,%3};"
                    : "+f"(acc[2 * ntp][0]), "+f"(acc[2 * ntp][1]),
                      "+f"(acc[2 * ntp][2]), "+f"(acc[2 * ntp][3])
                    : "r"(a0), "r"(a1), "r"(a2), "r"(a3),
                      "r"(r0), "r"(r1));
                asm volatile(
                    "mma.sync.aligned.m16n8k8.row.col.f32.tf32.tf32.f32 "
                    "{%0,%1,%2,%3}, {%4,%5,%6,%7}, {%8,%9}, {%0,%1,%2,%3};"
                    : "+f"(acc[2 * ntp + 1][0]), "+f"(acc[2 * ntp + 1][1]),
                      "+f"(acc[2 * ntp + 1][2]), "+f"(acc[2 * ntp + 1][3])
                    : "r"(a0), "r"(a1), "r"(a2), "r"(a3),
                      "r"(r2), "r"(r3));
            }
        }
    }

    // ---- epilogue: ctx[b, q, h*64 + d] = acc / l ----
    const float inv0 = 1.f / lr0;
    const float inv1 = 1.f / lr1;
    const int r0 = qt0 + wid * 16 + gid;
    const int r1 = r0 + 8;
#pragma unroll
    for (int nt = 0; nt < 8; nt++) {
        const int col = h * DEPTH + nt * 8 + tig * 2;
        float2 o0, o1;
        o0.x = acc[nt][0] * inv0; o0.y = acc[nt][1] * inv0;
        o1.x = acc[nt][2] * inv1; o1.y = acc[nt][3] * inv1;
        *(float2*)&ctx[(b * SLEN + r0) * DMODEL + col] = o0;
        *(float2*)&ctx[(b * SLEN + r1) * DMODEL + col] = o1;
    }
}

// ---------------------------------------------------------------------------
extern "C" void kernel_launch(void* const* d_in, const int* in_sizes, int n_in,
                              void* d_out, int out_size)
{
    const float* v    = (const float*)d_in[0];
    const float* k    = (const float*)d_in[1];
    const float* q    = (const float*)d_in[2];
    const int*   mask = (const int*)  d_in[3];
    const float* Wq   = (const float*)d_in[4];
    const float* bq   = (const float*)d_in[5];
    const float* Wk   = (const float*)d_in[6];
    const float* bk   = (const float*)d_in[7];
    const float* Wv   = (const float*)d_in[8];
    const float* bv   = (const float*)d_in[9];
    const float* Wo   = (const float*)d_in[10];
    const float* bo   = (const float*)d_in[11];
    float* out = (float*)d_out;

    float *qh, *kh, *vh, *ctx;
    cudaGetSymbolAddress((void**)&qh,  g_qh);
    cudaGetSymbolAddress((void**)&kh,  g_kh);
    cudaGetSymbolAddress((void**)&vh,  g_vh);
    cudaGetSymbolAddress((void**)&ctx, g_ctx);

    dim3 ggrid(DMODEL / 128, (BATCH * SLEN) / 128);   // (8, 64)

    gemm_tf32_kernel<<<ggrid, 256>>>(q, Wq, bq, qh, 1);
    gemm_tf32_kernel<<<ggrid, 256>>>(k, Wk, bk, kh, 1);
    gemm_tf32_kernel<<<ggrid, 256>>>(v, Wv, bv, vh, 2);

    attn_mma_kernel<<<dim3(SLEN / 128, NHEADS, BATCH), 256>>>(qh, kh, vh, mask, ctx);

    gemm_tf32_kernel<<<ggrid, 256>>>(ctx, Wo, bo, out, 0);
}

// round 9
// speedup vs baseline: 8.3165x; 1.0500x over previous
#include <cuda_runtime.h>
#include <cstdint>

// ---------------------------------------------------------------------------
// MultiHeadAttention forward.
//   B=4, S=2048, D=1024, H=16, depth=64
// Projections: tf32 mma.sync GEMMs; Q/K/V outputs pre-rounded to tf32 so the
// attention kernel is a pure-copy consumer.
// Attention: tf32 mma.sync flash attention, cp.async double-buffered K/V
// pipeline, conflict-free ldmatrix operand fragments, log2-domain softmax
// with polynomial exp2.
// ---------------------------------------------------------------------------

#define BATCH   4
#define SLEN    2048
#define DMODEL  1024
#define NHEADS  16
#define DEPTH   64
#define ELEMS   (BATCH * SLEN * DMODEL)

__device__ float g_qh[ELEMS];           // [B, H, S, depth]   (tf32 values)
__device__ float g_kh[ELEMS];           // [B, H, S, depth]   (tf32 values)
__device__ float g_vh[ELEMS];           // [B, H, depth, S]   (tf32 values)
__device__ float g_ctx[ELEMS];          // [B, S, D]
__device__ float g_mskf[BATCH * SLEN];  // mask * -1e9 * log2(e)

__device__ __forceinline__ float to_tf32(float x) {
    float y;
    asm("cvt.rna.tf32.f32 %0, %1;" : "=f"(y) : "f"(x));
    return y;
}

// exp2 without MUFU: round via magic constant, deg-5 Taylor on [-0.5,0.5].
__device__ __forceinline__ float exp2p(float t) {
    t = fmaxf(t, -100.0f);
    const float MAGIC = 12582912.0f;            // 2^23 + 2^22
    float r = t + MAGIC;
    int   ib = __float_as_int(r) << 23;
    float f = t - (r - MAGIC);
    float p = 0.00133335581f;
    p = fmaf(p, f, 0.00961812911f);
    p = fmaf(p, f, 0.05550410866f);
    p = fmaf(p, f, 0.24022650700f);
    p = fmaf(p, f, 0.69314718056f);
    p = fmaf(p, f, 1.0f);
    return __int_as_float(__float_as_int(p) + ib);
}

#define CP16(dst_u32, src_ptr) \
    asm volatile("cp.async.cg.shared.global [%0], [%1], 16;" \
                 :: "r"(dst_u32), "l"(src_ptr))
#define CP_COMMIT() asm volatile("cp.async.commit_group;")
#define CP_WAIT(n)  asm volatile("cp.async.wait_group %0;" :: "n"(n))

// ---------------------------------------------------------------------------
// Mask pre-scale: mskf = mask * (-1e9 * log2(e))
// ---------------------------------------------------------------------------
#define MASKC (-1.44269504e9f)
__global__ void mask_scale_kernel(const int* __restrict__ mask,
                                  float* __restrict__ mskf)
{
    const int i = blockIdx.x * 256 + threadIdx.x;
    if (i < BATCH * SLEN) mskf[i] = MASKC * (float)mask[i];
}

// ---------------------------------------------------------------------------
// tf32 GEMM: C = A[8192,1024] @ W[1024,1024] + bias.
// mode: 0 = row-major C (final output, full fp32);
//       1 = split-heads [B,H,S,d], tf32-rounded output;
//       2 = split-heads transposed [B,H,d,S], tf32-rounded output (V).
// ---------------------------------------------------------------------------
#define BK 32
#define LDA 36
#define LDB 136

__global__ __launch_bounds__(256, 2)
void gemm_tf32_kernel(const float* __restrict__ A,
                      const float* __restrict__ W,
                      const float* __restrict__ bias,
                      float* __restrict__ C,
                      int mode)
{
    const int K = DMODEL, N = DMODEL;
    __shared__ float As[128][LDA];
    __shared__ float Bs[BK][LDB];

    const int tid    = threadIdx.x;
    const int lane   = tid & 31;
    const int wid    = tid >> 5;
    const int warp_m = wid >> 1;
    const int warp_n = wid & 1;
    const int gid    = lane >> 2;
    const int tig    = lane & 3;

    const int bm = blockIdx.y * 128;
    const int bn = blockIdx.x * 128;

    const int arow  = tid >> 3;
    const int akf4  = (tid & 7) * 4;
    const int bkrow = tid >> 5;
    const int bnf4  = (tid & 31) * 4;

    const int lrow  = warp_m * 32 + (lane & 15);
    const int lhalf = (lane >> 4) * 4;

    float acc[2][8][4];
#pragma unroll
    for (int i = 0; i < 2; i++)
#pragma unroll
        for (int j = 0; j < 8; j++)
#pragma unroll
            for (int v = 0; v < 4; v++) acc[i][j][v] = 0.f;

    for (int k0 = 0; k0 < K; k0 += BK) {
        float4 pa[4], pb[4];
#pragma unroll
        for (int it = 0; it < 4; it++) {
            pa[it] = *(const float4*)(A + (bm + arow + it * 32) * K + k0 + akf4);
            pb[it] = *(const float4*)(W + (k0 + bkrow + it * 8) * N + bn + bnf4);
        }
        __syncthreads();
#pragma unroll
        for (int it = 0; it < 4; it++) {
            float4 a = pa[it];
            a.x = to_tf32(a.x); a.y = to_tf32(a.y);
            a.z = to_tf32(a.z); a.w = to_tf32(a.w);
            *(float4*)&As[arow + it * 32][akf4] = a;
            float4 b = pb[it];
            b.x = to_tf32(b.x); b.y = to_tf32(b.y);
            b.z = to_tf32(b.z); b.w = to_tf32(b.w);
            *(float4*)&Bs[bkrow + it * 8][bnf4] = b;
        }
        __syncthreads();

#pragma unroll
        for (int ks = 0; ks < 4; ks++) {
            const int k8 = ks * 8;
            uint32_t af[2][4];
#pragma unroll
            for (int mt = 0; mt < 2; mt++) {
                uint32_t saddr = (uint32_t)__cvta_generic_to_shared(
                    &As[lrow + mt * 16][k8 + lhalf]);
                asm volatile(
                    "ldmatrix.sync.aligned.m8n8.x4.shared.b16 {%0,%1,%2,%3}, [%4];"
                    : "=r"(af[mt][0]), "=r"(af[mt][1]),
                      "=r"(af[mt][2]), "=r"(af[mt][3])
                    : "r"(saddr));
            }
#pragma unroll
            for (int j = 0; j < 8; j++) {
                const int ncol = warp_n * 64 + j * 8 + gid;
                uint32_t b0 = __float_as_uint(Bs[k8 + tig][ncol]);
                uint32_t b1 = __float_as_uint(Bs[k8 + tig + 4][ncol]);
#pragma unroll
                for (int mt = 0; mt < 2; mt++) {
                    asm volatile(
                        "mma.sync.aligned.m16n8k8.row.col.f32.tf32.tf32.f32 "
                        "{%0,%1,%2,%3}, {%4,%5,%6,%7}, {%8,%9}, {%0,%1,%2,%3};"
                        : "+f"(acc[mt][j][0]), "+f"(acc[mt][j][1]),
                          "+f"(acc[mt][j][2]), "+f"(acc[mt][j][3])
                        : "r"(af[mt][0]), "r"(af[mt][1]),
                          "r"(af[mt][2]), "r"(af[mt][3]),
                          "r"(b0), "r"(b1));
                }
            }
        }
    }

#pragma unroll
    for (int mt = 0; mt < 2; mt++) {
        const int row0 = bm + warp_m * 32 + mt * 16 + gid;
#pragma unroll
        for (int j = 0; j < 8; j++) {
            const int gcol = bn + warp_n * 64 + j * 8 + tig * 2;
            const float bz0 = bias[gcol], bz1 = bias[gcol + 1];
#pragma unroll
            for (int half = 0; half < 2; half++) {
                const int grow = row0 + half * 8;
                float2 rv;
                rv.x = acc[mt][j][half * 2 + 0] + bz0;
                rv.y = acc[mt][j][half * 2 + 1] + bz1;
                if (mode != 0) {                 // attention inputs: tf32 values
                    rv.x = to_tf32(rv.x);
                    rv.y = to_tf32(rv.y);
                }
                if (mode == 1) {
                    const int bb = grow >> 11;
                    const int ss = grow & (SLEN - 1);
                    const int hh = gcol >> 6;
                    const int dd = gcol & (DEPTH - 1);
                    *(float2*)&C[(((bb * NHEADS + hh) * SLEN) + ss) * DEPTH + dd] = rv;
                } else if (mode == 2) {
                    const int bb = grow >> 11;
                    const int ss = grow & (SLEN - 1);
                    const int hh = gcol >> 6;
                    const int dd = gcol & (DEPTH - 1);
                    float* p = &C[(((bb * NHEADS + hh) * DEPTH) + dd) * SLEN + ss];
                    p[0]    = rv.x;
                    p[SLEN] = rv.y;
                } else {
                    *(float2*)&C[grow * DMODEL + gcol] = rv;
                }
            }
        }
    }
}

// ---------------------------------------------------------------------------
// Tensor-core flash attention (tf32 mma, fp32 accumulate).
// Grid (S/128, H, B), 256 threads = 8 warps; warp owns 16 query rows.
// K-tile = 64 keys. cp.async double-buffered K/V (+mask) pipeline.
// Dynamic smem layout (floats):
//   [0, 8704)      buffer 0:  K[64][68] then V[64][68]   (also Q[128][68])
//   [8704, 17408)  buffer 1:  K[64][68] then V[64][68]
//   [17408, 17536) mask tiles: [2][64]
// ---------------------------------------------------------------------------
#define SCL 0.18033688f          // 0.125 * log2(e)
#define LDS68 68
#define BUFF  8704               // 128*68
#define VOFF  4352               // 64*68
#define MOFF  17408
#define NT    (SLEN / 64)
#define SMEM_BYTES ((MOFF + 2 * 64) * 4)

extern __shared__ float dsm[];

__global__ __launch_bounds__(256, 2)
void attn_mma_kernel(const float* __restrict__ qh,
                     const float* __restrict__ kh,
                     const float* __restrict__ vt,    // [B,H,depth,S]
                     const float* __restrict__ mskf,
                     float* __restrict__ ctx)
{
    const int tid  = threadIdx.x;
    const int lane = tid & 31;
    const int wid  = tid >> 5;
    const int gid  = lane >> 2;
    const int tig  = lane & 3;

    const int qt0 = blockIdx.x * 128;
    const int h   = blockIdx.y;
    const int b   = blockIdx.z;
    const int bh  = (b * NHEADS + h) * SLEN;
    const int vtb = (b * NHEADS + h) * DEPTH;

    // per-thread copy mapping: idx -> (row, c4)
    const int crow = tid >> 4;           // 0..15 (+16 per step)
    const int cc4  = (tid & 15) * 4;

    const uint32_t smbase = (uint32_t)__cvta_generic_to_shared(dsm);

    // ---- stage Q tile (values already tf32) into buffer0 region ----
#pragma unroll
    for (int i = 0; i < 8; i++) {
        const int row = crow + i * 16;   // 0..127
        CP16(smbase + (row * LDS68 + cc4) * 4,
             qh + (bh + qt0 + row) * DEPTH + cc4);
    }
    CP_COMMIT();
    CP_WAIT(0);
    __syncthreads();

    uint32_t qf[8][4];
    {
        const int lrow = wid * 16 + (lane & 15);
        const int lco  = (lane >> 4) * 4;
#pragma unroll
        for (int ks = 0; ks < 8; ks++) {
            uint32_t saddr = smbase + (lrow * LDS68 + ks * 8 + lco) * 4;
            asm volatile(
                "ldmatrix.sync.aligned.m8n8.x4.shared.b16 {%0,%1,%2,%3}, [%4];"
                : "=r"(qf[ks][0]), "=r"(qf[ks][1]),
                  "=r"(qf[ks][2]), "=r"(qf[ks][3])
                : "r"(saddr));
        }
    }
    __syncthreads();    // all warps done with Q before buffer0 is overwritten

    // ---- issue tiles 0 and 1 ----
#pragma unroll
    for (int pre = 0; pre < 2; pre++) {
        const uint32_t bb = smbase + pre * (BUFF * 4);
        const int kbase = (bh + pre * 64) * DEPTH;
#pragma unroll
        for (int i = 0; i < 4; i++) {
            const int row = crow + i * 16;
            CP16(bb + (row * LDS68 + cc4) * 4,
                 kh + kbase + row * DEPTH + cc4);
            CP16(bb + ((VOFF + row * LDS68) + cc4) * 4,
                 vt + (vtb + row) * SLEN + pre * 64 + cc4);
        }
        if (tid < 16)
            CP16(smbase + (MOFF + pre * 64 + tid * 4) * 4,
                 mskf + b * SLEN + pre * 64 + tid * 4);
        CP_COMMIT();
    }

    // b-frag ldmatrix lane mapping
    const int bf_row = (lane & 7) + ((lane >> 4) << 3);
    const int bf_c4  = ((lane >> 3) & 1) * 4;

    float acc[8][4];
#pragma unroll
    for (int nt = 0; nt < 8; nt++)
#pragma unroll
        for (int e = 0; e < 4; e++) acc[nt][e] = 0.f;
    float mr0 = -1e30f, mr1 = -1e30f;
    float lr0 = 0.f,    lr1 = 0.f;

    for (int kt = 0; kt < NT; kt++) {
        const int par = kt & 1;
        CP_WAIT(1);                    // tile kt resident
        __syncthreads();

        const uint32_t bb      = smbase + par * (BUFF * 4);
        const uint32_t kbase_s = bb + (bf_row * LDS68 + bf_c4) * 4;
        const uint32_t vbase_s = bb + ((VOFF + bf_row * LDS68) + bf_c4) * 4;
        const float*   msks    = dsm + MOFF + par * 64;

        // ---- S = Q @ K^T ----
        float s[8][4];
#pragma unroll
        for (int nt = 0; nt < 8; nt++)
#pragma unroll
            for (int e = 0; e < 4; e++) s[nt][e] = 0.f;
#pragma unroll
        for (int k8 = 0; k8 < 8; k8++) {
#pragma unroll
            for (int ntp = 0; ntp < 4; ntp++) {
                uint32_t r0, r1, r2, r3;
                asm volatile(
                    "ldmatrix.sync.aligned.m8n8.x4.shared.b16 {%0,%1,%2,%3}, [%4];"
                    : "=r"(r0), "=r"(r1), "=r"(r2), "=r"(r3)
                    : "r"(kbase_s + ntp * (16 * LDS68 * 4) + k8 * 32));
                asm volatile(
                    "mma.sync.aligned.m16n8k8.row.col.f32.tf32.tf32.f32 "
                    "{%0,%1,%2,%3}, {%4,%5,%6,%7}, {%8,%9}, {%0,%1,%2,%3};"
                    : "+f"(s[2 * ntp][0]), "+f"(s[2 * ntp][1]),
                      "+f"(s[2 * ntp][2]), "+f"(s[2 * ntp][3])
                    : "r"(qf[k8][0]), "r"(qf[k8][1]),
                      "r"(qf[k8][2]), "r"(qf[k8][3]),
                      "r"(r0), "r"(r1));
                asm volatile(
                    "mma.sync.aligned.m16n8k8.row.col.f32.tf32.tf32.f32 "
                    "{%0,%1,%2,%3}, {%4,%5,%6,%7}, {%8,%9}, {%0,%1,%2,%3};"
                    : "+f"(s[2 * ntp + 1][0]), "+f"(s[2 * ntp + 1][1]),
                      "+f"(s[2 * ntp + 1][2]), "+f"(s[2 * ntp + 1][3])
                    : "r"(qf[k8][0]), "r"(qf[k8][1]),
                      "r"(qf[k8][2]), "r"(qf[k8][3]),
                      "r"(r2), "r"(r3));
            }
        }

        // ---- scale to log2 domain + mask, row max ----
        float tm0 = -1e30f, tm1 = -1e30f;
#pragma unroll
        for (int nt = 0; nt < 8; nt++) {
            const float mk0 = msks[nt * 8 + tig * 2];
            const float mk1 = msks[nt * 8 + tig * 2 + 1];
            s[nt][0] = fmaf(s[nt][0], SCL, mk0);
            s[nt][1] = fmaf(s[nt][1], SCL, mk1);
            s[nt][2] = fmaf(s[nt][2], SCL, mk0);
            s[nt][3] = fmaf(s[nt][3], SCL, mk1);
            tm0 = fmaxf(tm0, fmaxf(s[nt][0], s[nt][1]));
            tm1 = fmaxf(tm1, fmaxf(s[nt][2], s[nt][3]));
        }
        tm0 = fmaxf(tm0, __shfl_xor_sync(0xffffffffu, tm0, 1));
        tm0 = fmaxf(tm0, __shfl_xor_sync(0xffffffffu, tm0, 2));
        tm1 = fmaxf(tm1, __shfl_xor_sync(0xffffffffu, tm1, 1));
        tm1 = fmaxf(tm1, __shfl_xor_sync(0xffffffffu, tm1, 2));

        const float mn0 = fmaxf(mr0, tm0);
        const float mn1 = fmaxf(mr1, tm1);
        const float c0  = exp2p(mr0 - mn0);
        const float c1  = exp2p(mr1 - mn1);

        float rs0 = 0.f, rs1 = 0.f;
#pragma unroll
        for (int nt = 0; nt < 8; nt++) {
            float p0 = exp2p(s[nt][0] - mn0);
            float p1 = exp2p(s[nt][1] - mn0);
            float p2 = exp2p(s[nt][2] - mn1);
            float p3 = exp2p(s[nt][3] - mn1);
            rs0 += p0 + p1;
            rs1 += p2 + p3;
            s[nt][0] = to_tf32(p0);
            s[nt][1] = to_tf32(p1);
            s[nt][2] = to_tf32(p2);
            s[nt][3] = to_tf32(p3);
        }
        rs0 += __shfl_xor_sync(0xffffffffu, rs0, 1);
        rs0 += __shfl_xor_sync(0xffffffffu, rs0, 2);
        rs1 += __shfl_xor_sync(0xffffffffu, rs1, 1);
        rs1 += __shfl_xor_sync(0xffffffffu, rs1, 2);
        lr0 = lr0 * c0 + rs0;
        lr1 = lr1 * c1 + rs1;
        mr0 = mn0;
        mr1 = mn1;
#pragma unroll
        for (int nt = 0; nt < 8; nt++) {
            acc[nt][0] *= c0; acc[nt][1] *= c0;
            acc[nt][2] *= c1; acc[nt][3] *= c1;
        }

        // ---- acc += P @ V : S-frag -> a-frag via shuffles; V via ldmatrix ----
        const int src0 = gid * 4 + (tig >> 1);
        const int src1 = src0 + 2;
        const bool odd = (tig & 1);
#pragma unroll
        for (int kc = 0; kc < 8; kc++) {
            float x0 = __shfl_sync(0xffffffffu, s[kc][0], src0);
            float x1 = __shfl_sync(0xffffffffu, s[kc][1], src0);
            float x2 = __shfl_sync(0xffffffffu, s[kc][2], src0);
            float x3 = __shfl_sync(0xffffffffu, s[kc][3], src0);
            float y0 = __shfl_sync(0xffffffffu, s[kc][0], src1);
            float y1 = __shfl_sync(0xffffffffu, s[kc][1], src1);
            float y2 = __shfl_sync(0xffffffffu, s[kc][2], src1);
            float y3 = __shfl_sync(0xffffffffu, s[kc][3], src1);
            uint32_t a0 = __float_as_uint(odd ? x1 : x0);
            uint32_t a1 = __float_as_uint(odd ? x3 : x2);
            uint32_t a2 = __float_as_uint(odd ? y1 : y0);
            uint32_t a3 = __float_as_uint(odd ? y3 : y2);
#pragma unroll
            for (int ntp = 0; ntp < 4; ntp++) {
                uint32_t r0, r1, r2, r3;
                asm volatile(
                    "ldmatrix.sync.aligned.m8n8.x4.shared.b16 {%0,%1,%2,%3}, [%4];"
                    : "=r"(r0), "=r"(r1), "=r"(r2), "=r"(r3)
                    : "r"(vbase_s + ntp * (16 * LDS68 * 4) + kc * 32));
                asm volatile(
                    "mma.sync.aligned.m16n8k8.row.col.f32.tf32.tf32.f32 "
                    "{%0,%1,%2,%3}, {%4,%5,%6,%7}, {%8,%9}, {%0,%1,%2,%3};"
                    : "+f"(acc[2 * ntp][0]), "+f"(acc[2 * ntp][1]),
                      "+f"(acc[2 * ntp][2]), "+f"(acc[2 * ntp][3])
                    : "r"(a0), "r"(a1), "r"(a2), "r"(a3),
                      "r"(r0), "r"(r1));
                asm volatile(
                    "mma.sync.aligned.m16n8k8.row.col.f32.tf32.tf32.f32 "
                    "{%0,%1,%2,%3}, {%4,%5,%6,%7}, {%8,%9}, {%0,%1,%2,%3};"
                    : "+f"(acc[2 * ntp + 1][0]), "+f"(acc[2 * ntp + 1][1]),
                      "+f"(acc[2 * ntp + 1][2]), "+f"(acc[2 * ntp + 1][3])
                    : "r"(a0), "r"(a1), "r"(a2), "r"(a3),
                      "r"(r2), "r"(r3));
            }
        }

        __syncthreads();               // everyone done reading buf[par]
        // ---- refill buf[par] with tile kt+2 (commit a group regardless) ----
        if (kt + 2 < NT) {
            const int nk = kt + 2;
            const int kbase = (bh + nk * 64) * DEPTH;
#pragma unroll
            for (int i = 0; i < 4; i++) {
                const int row = crow + i * 16;
                CP16(bb + (row * LDS68 + cc4) * 4,
                     kh + kbase + row * DEPTH + cc4);
                CP16(bb + ((VOFF + row * LDS68) + cc4) * 4,
                     vt + (vtb + row) * SLEN + nk * 64 + cc4);
            }
            if (tid < 16)
                CP16(smbase + (MOFF + par * 64 + tid * 4) * 4,
                     mskf + b * SLEN + nk * 64 + tid * 4);
        }
        CP_COMMIT();
    }

    // ---- epilogue: ctx[b, q, h*64 + d] = acc / l ----
    const float inv0 = 1.f / lr0;
    const float inv1 = 1.f / lr1;
    const int r0 = qt0 + wid * 16 + gid;
    const int r1 = r0 + 8;
#pragma unroll
    for (int nt = 0; nt < 8; nt++) {
        const int col = h * DEPTH + nt * 8 + tig * 2;
        float2 o0, o1;
        o0.x = acc[nt][0] * inv0; o0.y = acc[nt][1] * inv0;
        o1.x = acc[nt][2] * inv1; o1.y = acc[nt][3] * inv1;
        *(float2*)&ctx[(b * SLEN + r0) * DMODEL + col] = o0;
        *(float2*)&ctx[(b * SLEN + r1) * DMODEL + col] = o1;
    }
}

// ---------------------------------------------------------------------------
extern "C" void kernel_launch(void* const* d_in, const int* in_sizes, int n_in,
                              void* d_out, int out_size)
{
    const float* v    = (const float*)d_in[0];
    const float* k    = (const float*)d_in[1];
    const float* q    = (const float*)d_in[2];
    const int*   mask = (const int*)  d_in[3];
    const float* Wq   = (const float*)d_in[4];
    const float* bq   = (const float*)d_in[5];
    const float* Wk   = (const float*)d_in[6];
    const float* bk   = (const float*)d_in[7];
    const float* Wv   = (const float*)d_in[8];
    const float* bv   = (const float*)d_in[9];
    const float* Wo   = (const float*)d_in[10];
    const float* bo   = (const float*)d_in[11];
    float* out = (float*)d_out;

    float *qh, *kh, *vh, *ctx, *mskf;
    cudaGetSymbolAddress((void**)&qh,   g_qh);
    cudaGetSymbolAddress((void**)&kh,   g_kh);
    cudaGetSymbolAddress((void**)&vh,   g_vh);
    cudaGetSymbolAddress((void**)&ctx,  g_ctx);
    cudaGetSymbolAddress((void**)&mskf, g_mskf);

    // Unconditional (idempotent, immediate, not stream-ordered): no static
    // guards allowed in kernel_launch.
    cudaFuncSetAttribute(attn_mma_kernel,
                         cudaFuncAttributeMaxDynamicSharedMemorySize,
                         SMEM_BYTES);

    dim3 ggrid(DMODEL / 128, (BATCH * SLEN) / 128);   // (8, 64)

    mask_scale_kernel<<<(BATCH * SLEN + 255) / 256, 256>>>(mask, mskf);
    gemm_tf32_kernel<<<ggrid, 256>>>(q, Wq, bq, qh, 1);
    gemm_tf32_kernel<<<ggrid, 256>>>(k, Wk, bk, kh, 1);
    gemm_tf32_kernel<<<ggrid, 256>>>(v, Wv, bv, vh, 2);

    attn_mma_kernel<<<dim3(SLEN / 128, NHEADS, BATCH), 256, SMEM_BYTES>>>(
        qh, kh, vh, mskf, ctx);

    gemm_tf32_kernel<<<ggrid, 256>>>(ctx, Wo, bo, out, 0);
}